// round 1
// baseline (speedup 1.0000x reference)
#include <cuda_runtime.h>
#include <cstdint>

#define NN   50000
#define DD   128
#define EMAX 1600000

// ---------------- device scratch (static: no allocation allowed) ----------
__device__ __align__(16) float g_deg[NN];
__device__ __align__(16) float g_dinv[NN];
__device__ __align__(16) float g_h[(size_t)NN * DD];
__device__ __align__(16) float g_agg[(size_t)NN * DD];
__device__ __align__(16) float g_x2[(size_t)NN * DD];
__device__ int g_src[EMAX];
__device__ int g_dst[EMAX];
__device__ int g_is64;

// ---------------- dtype detection: int64 vs int32 edge_index --------------
// Node ids < 50000 < 2^31, so for int64 data every odd 32-bit word is 0.
// For int32 data the odd words are random indices -> P(all zero) ~ 0.
__global__ void k_detect(const int* __restrict__ ei) {
    int is64 = 1;
    for (int i = 1; i < 64; i += 2)
        if (ei[i] != 0) { is64 = 0; break; }
    g_is64 = is64;
}

__global__ void k_convert(const void* __restrict__ ei, int E) {
    int i = blockIdx.x * blockDim.x + threadIdx.x;
    if (i >= E) return;
    if (g_is64) {
        const long long* p = (const long long*)ei;
        g_src[i] = (int)p[i];
        g_dst[i] = (int)p[(size_t)E + i];
    } else {
        const int* p = (const int*)ei;
        g_src[i] = p[i];
        g_dst[i] = p[(size_t)E + i];
    }
}

// ---------------- degree / norm -------------------------------------------
__global__ void k_deg_init(int N) {
    int i = blockIdx.x * blockDim.x + threadIdx.x;
    if (i < N) g_deg[i] = 1.0f;          // self-loop
}

__global__ void k_deg(int E) {
    int i = blockIdx.x * blockDim.x + threadIdx.x;
    if (i < E) atomicAdd(&g_deg[g_dst[i]], 1.0f);
}

__global__ void k_dinv(int N) {
    int i = blockIdx.x * blockDim.x + threadIdx.x;
    if (i < N) g_dinv[i] = rsqrtf(g_deg[i]);
}

// ---------------- GEMM: H[N,128] = X[N,128] @ W[128,128] ------------------
// 256 threads/block, 32 rows/block. W chunked in k (2 x 64) into smem,
// X tile stored transposed Xs[k][r]. Each thread: 4 rows x 4 cols.
__global__ void __launch_bounds__(256) k_gemm(
    const float* __restrict__ X, const float* __restrict__ W,
    float* __restrict__ H, int N)
{
    __shared__ float Ws[64 * 128];   // 32 KB
    __shared__ float Xs[64 * 32];    // 8 KB
    const int tx = threadIdx.x;
    const int row0 = blockIdx.x * 32;
    const int cg = tx & 31;          // col group -> cols cg*4 .. cg*4+3
    const int rg = tx >> 5;          // row group -> rows rg*4 .. rg*4+3

    float acc[4][4] = {};

    for (int kb = 0; kb < 128; kb += 64) {
        // load W chunk (coalesced float4)
        const float4* Wg = (const float4*)(W + (size_t)kb * 128);
        float4* Wsv = (float4*)Ws;
#pragma unroll
        for (int i = 0; i < 8; ++i) Wsv[tx + i * 256] = Wg[tx + i * 256];

        // load X tile transposed: Xs[k][r] = X[row0+r][kb+k]
        {
            const int r = tx & 31;
            const int kq = tx >> 5;          // 0..7, k = kq*8 .. kq*8+7
            const int grow = row0 + r;
            float v[8];
            if (grow < N) {
                float4 a = *(const float4*)(X + (size_t)grow * 128 + kb + kq * 8);
                float4 b = *(const float4*)(X + (size_t)grow * 128 + kb + kq * 8 + 4);
                v[0]=a.x; v[1]=a.y; v[2]=a.z; v[3]=a.w;
                v[4]=b.x; v[5]=b.y; v[6]=b.z; v[7]=b.w;
            } else {
#pragma unroll
                for (int q = 0; q < 8; ++q) v[q] = 0.f;
            }
#pragma unroll
            for (int q = 0; q < 8; ++q) Xs[(kq * 8 + q) * 32 + r] = v[q];
        }
        __syncthreads();

#pragma unroll 16
        for (int k = 0; k < 64; ++k) {
            float4 w  = *(const float4*)&Ws[k * 128 + cg * 4];
            float4 xv = *(const float4*)&Xs[k * 32 + rg * 4];
            float wv[4] = {w.x, w.y, w.z, w.w};
            float xr[4] = {xv.x, xv.y, xv.z, xv.w};
#pragma unroll
            for (int i = 0; i < 4; ++i)
#pragma unroll
                for (int j = 0; j < 4; ++j)
                    acc[i][j] = fmaf(xr[i], wv[j], acc[i][j]);
        }
        __syncthreads();
    }

#pragma unroll
    for (int i = 0; i < 4; ++i) {
        int grow = row0 + rg * 4 + i;
        if (grow < N) {
            float4 o = make_float4(acc[i][0], acc[i][1], acc[i][2], acc[i][3]);
            *(float4*)(H + (size_t)grow * 128 + cg * 4) = o;
        }
    }
}

// ---------------- agg init: self-loop term + bias --------------------------
__global__ void k_selfbias(const float* __restrict__ h, const float* __restrict__ b,
                           float* __restrict__ agg, int N)
{
    int idx = blockIdx.x * blockDim.x + threadIdx.x;   // float4 index
    if (idx >= N * 32) return;
    int row = idx >> 5;
    int c4  = idx & 31;
    float di = g_dinv[row];
    float s  = di * di;
    float4 hv = ((const float4*)h)[idx];
    float4 bv = ((const float4*)b)[c4];
    ((float4*)agg)[idx] = make_float4(fmaf(hv.x, s, bv.x), fmaf(hv.y, s, bv.y),
                                      fmaf(hv.z, s, bv.z), fmaf(hv.w, s, bv.w));
}

// ---------------- edge scatter: agg[dst] += h[src] * norm -----------------
__device__ __forceinline__ void red_add_v4(float* addr, float a, float b, float c, float d) {
#if __CUDA_ARCH__ >= 900
    asm volatile("red.global.add.v4.f32 [%0], {%1, %2, %3, %4};"
                 :: "l"(addr), "f"(a), "f"(b), "f"(c), "f"(d) : "memory");
#else
    atomicAdd(addr + 0, a); atomicAdd(addr + 1, b);
    atomicAdd(addr + 2, c); atomicAdd(addr + 3, d);
#endif
}

__global__ void __launch_bounds__(256) k_scatter(
    const float* __restrict__ h, float* __restrict__ agg, int E)
{
    int gtid = blockIdx.x * blockDim.x + threadIdx.x;
    int w = gtid >> 5;
    int lane = gtid & 31;
    if (w >= E) return;
    int s = g_src[w];
    int d = g_dst[w];
    float nrm = g_dinv[s] * g_dinv[d];
    float4 v = ((const float4*)(h + (size_t)s * DD))[lane];
    float* ap = agg + (size_t)d * DD + lane * 4;
    red_add_v4(ap, v.x * nrm, v.y * nrm, v.z * nrm, v.w * nrm);
}

// ---------------- fused LayerNorm + ELU (one warp per row) ----------------
__global__ void __launch_bounds__(256) k_lnelu(
    const float* __restrict__ in, const float* __restrict__ gma,
    const float* __restrict__ bet, float* __restrict__ out, int N)
{
    int gtid = blockIdx.x * blockDim.x + threadIdx.x;
    int row = gtid >> 5;
    int lane = gtid & 31;
    if (row >= N) return;
    float4 v = ((const float4*)(in + (size_t)row * DD))[lane];
    float s  = v.x + v.y + v.z + v.w;
    float sq = v.x*v.x + v.y*v.y + v.z*v.z + v.w*v.w;
#pragma unroll
    for (int o = 16; o; o >>= 1) {
        s  += __shfl_xor_sync(0xFFFFFFFFu, s,  o);
        sq += __shfl_xor_sync(0xFFFFFFFFu, sq, o);
    }
    float mean = s * (1.0f / 128.0f);
    float var  = sq * (1.0f / 128.0f) - mean * mean;
    float rstd = rsqrtf(var + 1e-5f);
    float4 g = ((const float4*)gma)[lane];
    float4 b = ((const float4*)bet)[lane];
    float4 o;
    {
        float t;
        t = (v.x - mean) * rstd * g.x + b.x; o.x = t > 0.f ? t : expm1f(t);
        t = (v.y - mean) * rstd * g.y + b.y; o.y = t > 0.f ? t : expm1f(t);
        t = (v.z - mean) * rstd * g.z + b.z; o.z = t > 0.f ? t : expm1f(t);
        t = (v.w - mean) * rstd * g.w + b.w; o.w = t > 0.f ? t : expm1f(t);
    }
    ((float4*)(out + (size_t)row * DD))[lane] = o;
}

// ---------------- launch ----------------------------------------------------
extern "C" void kernel_launch(void* const* d_in, const int* in_sizes, int n_in,
                              void* d_out, int out_size)
{
    const float* x   = (const float*)d_in[0];
    const void*  ei  = d_in[1];
    const float* W1  = (const float*)d_in[2];
    const float* b1  = (const float*)d_in[3];
    const float* g1  = (const float*)d_in[4];
    const float* be1 = (const float*)d_in[5];
    const float* W2  = (const float*)d_in[6];
    const float* b2  = (const float*)d_in[7];
    const float* g2  = (const float*)d_in[8];
    const float* be2 = (const float*)d_in[9];

    int N = in_sizes[0] / DD;  if (N > NN)   N = NN;
    int E = in_sizes[1] / 2;   if (E > EMAX) E = EMAX;
    float* out = (float*)d_out;

    float *h, *agg, *x2;
    cudaGetSymbolAddress((void**)&h,   g_h);
    cudaGetSymbolAddress((void**)&agg, g_agg);
    cudaGetSymbolAddress((void**)&x2,  g_x2);

    const int T = 256;
    int ebl  = (E + T - 1) / T;
    int nbl  = (N + T - 1) / T;
    int sbl  = (E + 7) / 8;          // 8 warps/block, 1 warp/edge
    int fbl  = (N * 32 + T - 1) / T; // float4 granularity over N*128
    int lbl  = (N + 7) / 8;          // 1 warp/row
    int gbl  = (N + 31) / 32;        // 32 rows/block

    // graph preprocessing
    k_detect<<<1, 1>>>((const int*)ei);
    k_convert<<<ebl, T>>>(ei, E);
    k_deg_init<<<nbl, T>>>(N);
    k_deg<<<ebl, T>>>(E);
    k_dinv<<<nbl, T>>>(N);

    // layer 1
    k_gemm<<<gbl, T>>>(x, W1, h, N);
    k_selfbias<<<fbl, T>>>(h, b1, agg, N);
    k_scatter<<<sbl, T>>>(h, agg, E);
    k_lnelu<<<lbl, T>>>(agg, g1, be1, x2, N);

    // layer 2
    k_gemm<<<gbl, T>>>(x2, W2, h, N);
    k_selfbias<<<fbl, T>>>(h, b2, agg, N);
    k_scatter<<<sbl, T>>>(h, agg, E);
    k_lnelu<<<lbl, T>>>(agg, g2, be2, out, N);
}

// round 2
// speedup vs baseline: 1.4886x; 1.4886x over previous
#include <cuda_runtime.h>
#include <cstdint>

#define NN   50000
#define DD   128
#define EMAX 1600000

// ---------------- device scratch (static: no allocation allowed) ----------
__device__ __align__(16) float g_dinv[NN];
__device__ int g_degi[NN];
__device__ int g_off[NN + 1];
__device__ int g_cur[NN];
__device__ int g_src[EMAX];
__device__ int g_dst[EMAX];
__device__ int g_csr[EMAX];
__device__ __align__(16) float g_hs[(size_t)NN * DD];
__device__ __align__(16) float g_x2[(size_t)NN * DD];
__device__ int g_is64;

// ---------------- dtype detection: int64 vs int32 edge_index --------------
// Node ids < 50000 < 2^31 and non-negative, so for int64 data every odd
// 32-bit word is 0. For int32 data the odd words are node ids (~0 prob all 0).
__global__ void k_detect(const unsigned* __restrict__ ei) {
    int lane = threadIdx.x;
    unsigned hi = ei[lane * 2 + 1];
    unsigned any = __ballot_sync(0xFFFFFFFFu, hi != 0u);
    if (lane == 0) g_is64 = (any == 0u) ? 1 : 0;
}

// convert to int32 + count in-degree
__global__ void k_convert(const void* __restrict__ ei, int E) {
    int i = blockIdx.x * blockDim.x + threadIdx.x;
    if (i >= E) return;
    int s, d;
    if (g_is64) {
        const long long* p = (const long long*)ei;
        s = (int)p[i];
        d = (int)p[(size_t)E + i];
    } else {
        const int* p = (const int*)ei;
        s = p[i];
        d = p[(size_t)E + i];
    }
    g_src[i] = s;
    g_dst[i] = d;
    atomicAdd(&g_degi[d], 1);
}

// ---------------- single-block scan: offsets, cursors, dinv ---------------
__global__ void __launch_bounds__(1024) k_scan(int N) {
    __shared__ int part[1024];
    const int t = threadIdx.x;
    const int C = (N + 1023) >> 10;
    const int lo = t * C;
    const int hi = min(lo + C, N);

    int s = 0;
    for (int i = lo; i < hi; ++i) s += g_degi[i];
    part[t] = s;
    __syncthreads();
    // Hillis-Steele inclusive scan
    for (int o = 1; o < 1024; o <<= 1) {
        int v = (t >= o) ? part[t - o] : 0;
        __syncthreads();
        part[t] += v;
        __syncthreads();
    }
    int run = (t > 0) ? part[t - 1] : 0;
    for (int i = lo; i < hi; ++i) {
        int dg = g_degi[i];
        g_off[i] = run;
        g_cur[i] = run;
        g_dinv[i] = rsqrtf((float)(dg + 1));   // +1 for self-loop
        run += dg;
    }
    if (t == 0) g_off[N] = part[1023];
}

// ---------------- CSR fill (counting sort of edges by dst) ----------------
__global__ void k_fill(int E) {
    int i = blockIdx.x * blockDim.x + threadIdx.x;
    if (i >= E) return;
    int d = g_dst[i];
    int pos = atomicAdd(&g_cur[d], 1);
    g_csr[pos] = g_src[i];
}

// ---------------- GEMM: HS[N,128] = (X[N,128] @ W[128,128]) * dinv[row] ---
// 256 threads/block, tile 128 rows x 128 cols, each thread 8x8 via
// packed fma.rn.f32x2 (4 col-pairs per row).
__global__ void __launch_bounds__(256) k_gemm(
    const float* __restrict__ X, const float* __restrict__ W,
    float* __restrict__ H, int N)
{
    __shared__ float Ws[32 * 128];   // [k][col]   16 KB
    __shared__ float Xs[32 * 128];   // [k][row]   16 KB
    const int tx = threadIdx.x;
    const int row0 = blockIdx.x * 128;
    const int cg = tx & 15;          // cols cg*8 .. cg*8+7
    const int rg = tx >> 4;          // rows rg*8 .. rg*8+7

    unsigned long long acc[8][4];
#pragma unroll
    for (int i = 0; i < 8; ++i)
#pragma unroll
        for (int j = 0; j < 4; ++j) acc[i][j] = 0ull;

    for (int kb = 0; kb < 128; kb += 32) {
        // W chunk: 32x128 floats, direct copy (coalesced float4)
        {
            const float4* Wg = (const float4*)(W + (size_t)kb * 128);
            float4* Wsv = (float4*)Ws;
#pragma unroll
            for (int i = 0; i < 4; ++i) Wsv[tx + i * 256] = Wg[tx + i * 256];
        }
        // X tile transposed: Xs[k][r], 128 rows x 32 k
        {
            const int r = tx & 127;
            const int half = tx >> 7;        // 0/1 -> k ranges [0,16) / [16,32)
            const int grow = row0 + r;
#pragma unroll
            for (int q = 0; q < 4; ++q) {
                int k = half * 16 + q * 4;
                float4 v = make_float4(0.f, 0.f, 0.f, 0.f);
                if (grow < N) v = *(const float4*)(X + (size_t)grow * 128 + kb + k);
                Xs[(k + 0) * 128 + r] = v.x;
                Xs[(k + 1) * 128 + r] = v.y;
                Xs[(k + 2) * 128 + r] = v.z;
                Xs[(k + 3) * 128 + r] = v.w;
            }
        }
        __syncthreads();

#pragma unroll
        for (int k = 0; k < 32; ++k) {
            ulonglong2 w01 = *(const ulonglong2*)&Ws[k * 128 + cg * 8];
            ulonglong2 w23 = *(const ulonglong2*)&Ws[k * 128 + cg * 8 + 4];
            float4 x0 = *(const float4*)&Xs[k * 128 + rg * 8];
            float4 x1 = *(const float4*)&Xs[k * 128 + rg * 8 + 4];
            float xr[8] = {x0.x, x0.y, x0.z, x0.w, x1.x, x1.y, x1.z, x1.w};
#pragma unroll
            for (int i = 0; i < 8; ++i) {
                unsigned long long xx;
                asm("mov.b64 %0, {%1, %1};" : "=l"(xx) : "r"(__float_as_uint(xr[i])));
                asm("fma.rn.f32x2 %0, %1, %2, %0;" : "+l"(acc[i][0]) : "l"(xx), "l"(w01.x));
                asm("fma.rn.f32x2 %0, %1, %2, %0;" : "+l"(acc[i][1]) : "l"(xx), "l"(w01.y));
                asm("fma.rn.f32x2 %0, %1, %2, %0;" : "+l"(acc[i][2]) : "l"(xx), "l"(w23.x));
                asm("fma.rn.f32x2 %0, %1, %2, %0;" : "+l"(acc[i][3]) : "l"(xx), "l"(w23.y));
            }
        }
        __syncthreads();
    }

#pragma unroll
    for (int i = 0; i < 8; ++i) {
        int grow = row0 + rg * 8 + i;
        if (grow < N) {
            float sc = g_dinv[grow];
            float lo0 = __uint_as_float((unsigned)acc[i][0]);
            float hi0 = __uint_as_float((unsigned)(acc[i][0] >> 32));
            float lo1 = __uint_as_float((unsigned)acc[i][1]);
            float hi1 = __uint_as_float((unsigned)(acc[i][1] >> 32));
            float lo2 = __uint_as_float((unsigned)acc[i][2]);
            float hi2 = __uint_as_float((unsigned)(acc[i][2] >> 32));
            float lo3 = __uint_as_float((unsigned)acc[i][3]);
            float hi3 = __uint_as_float((unsigned)(acc[i][3] >> 32));
            float4 o0 = make_float4(lo0 * sc, hi0 * sc, lo1 * sc, hi1 * sc);
            float4 o1 = make_float4(lo2 * sc, hi2 * sc, lo3 * sc, hi3 * sc);
            *(float4*)(H + (size_t)grow * 128 + cg * 8) = o0;
            *(float4*)(H + (size_t)grow * 128 + cg * 8 + 4) = o1;
        }
    }
}

// --------- fused pull-aggregation + dinv scale + bias + LN + ELU ----------
// One warp per destination node. acc = hs[d] + sum_{s in nbrs(d)} hs[s];
// pre-LN t = acc * dinv[d] + b; then LN (gamma, beta) and ELU.
__global__ void __launch_bounds__(256) k_aggln(
    const float* __restrict__ hs, const float* __restrict__ bias,
    const float* __restrict__ gma, const float* __restrict__ bet,
    float* __restrict__ out, int N)
{
    int gt = blockIdx.x * blockDim.x + threadIdx.x;
    int row = gt >> 5;
    int lane = gt & 31;
    if (row >= N) return;

    const float4* hv = (const float4*)hs;
    float4 acc = __ldg(&hv[(size_t)row * 32 + lane]);   // self-loop term

    int e = g_off[row];
    const int end = g_off[row + 1];
    while (e < end) {
        int rem = end - e;
        int cnt = rem < 32 ? rem : 32;
        int idx = (lane < cnt) ? g_csr[e + lane] : 0;
#pragma unroll 4
        for (int j = 0; j < cnt; ++j) {
            int s = __shfl_sync(0xFFFFFFFFu, idx, j);
            float4 v = __ldg(&hv[(size_t)s * 32 + lane]);
            acc.x += v.x; acc.y += v.y; acc.z += v.z; acc.w += v.w;
        }
        e += cnt;
    }

    float sc = g_dinv[row];
    float4 b = ((const float4*)bias)[lane];
    float4 t;
    t.x = fmaf(acc.x, sc, b.x);
    t.y = fmaf(acc.y, sc, b.y);
    t.z = fmaf(acc.z, sc, b.z);
    t.w = fmaf(acc.w, sc, b.w);

    float s  = t.x + t.y + t.z + t.w;
    float sq = t.x * t.x + t.y * t.y + t.z * t.z + t.w * t.w;
#pragma unroll
    for (int o = 16; o; o >>= 1) {
        s  += __shfl_xor_sync(0xFFFFFFFFu, s,  o);
        sq += __shfl_xor_sync(0xFFFFFFFFu, sq, o);
    }
    float mean = s * (1.0f / 128.0f);
    float var  = sq * (1.0f / 128.0f) - mean * mean;
    float rstd = rsqrtf(var + 1e-5f);

    float4 g = ((const float4*)gma)[lane];
    float4 be = ((const float4*)bet)[lane];
    float4 o;
    float u;
    u = (t.x - mean) * rstd * g.x + be.x; o.x = u > 0.f ? u : expm1f(u);
    u = (t.y - mean) * rstd * g.y + be.y; o.y = u > 0.f ? u : expm1f(u);
    u = (t.z - mean) * rstd * g.z + be.z; o.z = u > 0.f ? u : expm1f(u);
    u = (t.w - mean) * rstd * g.w + be.w; o.w = u > 0.f ? u : expm1f(u);

    ((float4*)(out + (size_t)row * 128))[lane] = o;
}

// ---------------- launch ----------------------------------------------------
extern "C" void kernel_launch(void* const* d_in, const int* in_sizes, int n_in,
                              void* d_out, int out_size)
{
    const float* x   = (const float*)d_in[0];
    const void*  ei  = d_in[1];
    const float* W1  = (const float*)d_in[2];
    const float* b1  = (const float*)d_in[3];
    const float* g1  = (const float*)d_in[4];
    const float* be1 = (const float*)d_in[5];
    const float* W2  = (const float*)d_in[6];
    const float* b2  = (const float*)d_in[7];
    const float* g2  = (const float*)d_in[8];
    const float* be2 = (const float*)d_in[9];

    int N = in_sizes[0] / DD;  if (N > NN)   N = NN;
    int E = in_sizes[1] / 2;   if (E > EMAX) E = EMAX;
    float* out = (float*)d_out;

    float *hs, *x2;
    void* degi;
    cudaGetSymbolAddress((void**)&hs,  g_hs);
    cudaGetSymbolAddress((void**)&x2,  g_x2);
    cudaGetSymbolAddress(&degi, g_degi);

    const int T = 256;
    int ebl = (E + T - 1) / T;
    int abl = (N + 7) / 8;            // 1 warp/node
    int gbl = (N + 127) / 128;        // 128 rows/block

    // ---- graph preprocessing: CSR build + norms ----
    cudaMemsetAsync(degi, 0, (size_t)N * sizeof(int));
    k_detect<<<1, 32>>>((const unsigned*)ei);
    k_convert<<<ebl, T>>>(ei, E);
    k_scan<<<1, 1024>>>(N);
    k_fill<<<ebl, T>>>(E);

    // ---- layer 1 ----
    k_gemm<<<gbl, T>>>(x, W1, hs, N);
    k_aggln<<<abl, T>>>(hs, b1, g1, be1, x2, N);

    // ---- layer 2 ----
    k_gemm<<<gbl, T>>>(x2, W2, hs, N);
    k_aggln<<<abl, T>>>(hs, b2, g2, be2, out, N);
}

// round 3
// speedup vs baseline: 1.5530x; 1.0433x over previous
#include <cuda_runtime.h>
#include <cuda_fp16.h>
#include <cstdint>

#define NN   50000
#define DD   128
#define EMAX 1600000

// ---------------- device scratch (static: no allocation allowed) ----------
__device__ __align__(16) float g_dinv[NN];
__device__ int g_degi[NN];
__device__ int g_off[NN + 1];
__device__ int g_cur[NN];
__device__ int g_src[EMAX];
__device__ int g_dst[EMAX];
__device__ int g_csr[EMAX];
__device__ __align__(16) __half g_hs[(size_t)NN * DD];   // fp16 post-GEMM features
__device__ __align__(16) float g_x2[(size_t)NN * DD];
__device__ int g_is64;

// ---------------- dtype detection: int64 vs int32 edge_index --------------
__global__ void k_detect(const unsigned* __restrict__ ei) {
    int lane = threadIdx.x;
    unsigned hi = ei[lane * 2 + 1];
    unsigned any = __ballot_sync(0xFFFFFFFFu, hi != 0u);
    if (lane == 0) g_is64 = (any == 0u) ? 1 : 0;
}

// convert to int32 + count in-degree
__global__ void k_convert(const void* __restrict__ ei, int E) {
    int i = blockIdx.x * blockDim.x + threadIdx.x;
    if (i >= E) return;
    int s, d;
    if (g_is64) {
        const long long* p = (const long long*)ei;
        s = (int)p[i];
        d = (int)p[(size_t)E + i];
    } else {
        const int* p = (const int*)ei;
        s = p[i];
        d = p[(size_t)E + i];
    }
    g_src[i] = s;
    g_dst[i] = d;
    atomicAdd(&g_degi[d], 1);
}

// ---------------- single-block scan: offsets, cursors, dinv ---------------
__global__ void __launch_bounds__(1024) k_scan(int N) {
    __shared__ int part[1024];
    const int t = threadIdx.x;
    const int C = (N + 1023) >> 10;
    const int lo = t * C;
    const int hi = min(lo + C, N);

    int s = 0;
    for (int i = lo; i < hi; ++i) s += g_degi[i];
    part[t] = s;
    __syncthreads();
    for (int o = 1; o < 1024; o <<= 1) {
        int v = (t >= o) ? part[t - o] : 0;
        __syncthreads();
        part[t] += v;
        __syncthreads();
    }
    int run = (t > 0) ? part[t - 1] : 0;
    for (int i = lo; i < hi; ++i) {
        int dg = g_degi[i];
        g_off[i] = run;
        g_cur[i] = run;
        g_dinv[i] = rsqrtf((float)(dg + 1));   // +1 self-loop
        run += dg;
    }
    if (t == 0) g_off[N] = part[1023];
}

// ---------------- CSR fill (counting sort of edges by dst) ----------------
__global__ void k_fill(int E) {
    int i = blockIdx.x * blockDim.x + threadIdx.x;
    if (i >= E) return;
    int d = g_dst[i];
    int pos = atomicAdd(&g_cur[d], 1);
    g_csr[pos] = g_src[i];
}

// ---------------- GEMM: HS[N,128] = fp16((X @ W) * dinv[row]) -------------
// 256 threads/block, tile 128x128, thread tile 8x8 via fma.rn.f32x2.
__global__ void __launch_bounds__(256) k_gemm(
    const float* __restrict__ X, const float* __restrict__ W,
    __half* __restrict__ H, int N)
{
    __shared__ float Ws[32 * 128];   // [k][col]
    __shared__ float Xs[32 * 128];   // [k][row]
    const int tx = threadIdx.x;
    const int row0 = blockIdx.x * 128;
    const int cg = tx & 15;
    const int rg = tx >> 4;

    unsigned long long acc[8][4];
#pragma unroll
    for (int i = 0; i < 8; ++i)
#pragma unroll
        for (int j = 0; j < 4; ++j) acc[i][j] = 0ull;

    for (int kb = 0; kb < 128; kb += 32) {
        {
            const float4* Wg = (const float4*)(W + (size_t)kb * 128);
            float4* Wsv = (float4*)Ws;
#pragma unroll
            for (int i = 0; i < 4; ++i) Wsv[tx + i * 256] = Wg[tx + i * 256];
        }
        {
            const int r = tx & 127;
            const int half_ = tx >> 7;
            const int grow = row0 + r;
#pragma unroll
            for (int q = 0; q < 4; ++q) {
                int k = half_ * 16 + q * 4;
                float4 v = make_float4(0.f, 0.f, 0.f, 0.f);
                if (grow < N) v = *(const float4*)(X + (size_t)grow * 128 + kb + k);
                Xs[(k + 0) * 128 + r] = v.x;
                Xs[(k + 1) * 128 + r] = v.y;
                Xs[(k + 2) * 128 + r] = v.z;
                Xs[(k + 3) * 128 + r] = v.w;
            }
        }
        __syncthreads();

#pragma unroll
        for (int k = 0; k < 32; ++k) {
            ulonglong2 w01 = *(const ulonglong2*)&Ws[k * 128 + cg * 8];
            ulonglong2 w23 = *(const ulonglong2*)&Ws[k * 128 + cg * 8 + 4];
            float4 x0 = *(const float4*)&Xs[k * 128 + rg * 8];
            float4 x1 = *(const float4*)&Xs[k * 128 + rg * 8 + 4];
            float xr[8] = {x0.x, x0.y, x0.z, x0.w, x1.x, x1.y, x1.z, x1.w};
#pragma unroll
            for (int i = 0; i < 8; ++i) {
                unsigned long long xx;
                asm("mov.b64 %0, {%1, %1};" : "=l"(xx) : "r"(__float_as_uint(xr[i])));
                asm("fma.rn.f32x2 %0, %1, %2, %0;" : "+l"(acc[i][0]) : "l"(xx), "l"(w01.x));
                asm("fma.rn.f32x2 %0, %1, %2, %0;" : "+l"(acc[i][1]) : "l"(xx), "l"(w01.y));
                asm("fma.rn.f32x2 %0, %1, %2, %0;" : "+l"(acc[i][2]) : "l"(xx), "l"(w23.x));
                asm("fma.rn.f32x2 %0, %1, %2, %0;" : "+l"(acc[i][3]) : "l"(xx), "l"(w23.y));
            }
        }
        __syncthreads();
    }

#pragma unroll
    for (int i = 0; i < 8; ++i) {
        int grow = row0 + rg * 8 + i;
        if (grow < N) {
            float sc = g_dinv[grow];
            uint4 o;
            unsigned* op = (unsigned*)&o;
#pragma unroll
            for (int j = 0; j < 4; ++j) {
                float lo = __uint_as_float((unsigned)acc[i][j]) * sc;
                float hi = __uint_as_float((unsigned)(acc[i][j] >> 32)) * sc;
                __half2 h2 = __floats2half2_rn(lo, hi);
                op[j] = *(unsigned*)&h2;
            }
            *(uint4*)(H + (size_t)grow * 128 + cg * 8) = o;
        }
    }
}

// --------- fused pull-aggregation (fp16 gather) + bias + LN + ELU ---------
// One warp per destination node; lane owns 4 columns (2 half2 = 8 bytes).
__global__ void __launch_bounds__(256) k_aggln(
    const __half* __restrict__ hs, const float* __restrict__ bias,
    const float* __restrict__ gma, const float* __restrict__ bet,
    float* __restrict__ out, int N)
{
    int gt = blockIdx.x * blockDim.x + threadIdx.x;
    int row = gt >> 5;
    int lane = gt & 31;
    if (row >= N) return;

    const uint2* hv = (const uint2*)hs;   // 4 halfs per lane slot; 32 slots/row

    // self-loop term
    float4 acc;
    {
        uint2 p = __ldg(&hv[(size_t)row * 32 + lane]);
        float2 a = __half22float2(*(__half2*)&p.x);
        float2 b = __half22float2(*(__half2*)&p.y);
        acc = make_float4(a.x, a.y, b.x, b.y);
    }

    int e = g_off[row];
    const int end = g_off[row + 1];
    while (e < end) {
        int rem = end - e;
        int cnt = rem < 32 ? rem : 32;
        int idx = (lane < cnt) ? g_csr[e + lane] : 0;
#pragma unroll 4
        for (int j = 0; j < cnt; ++j) {
            int s = __shfl_sync(0xFFFFFFFFu, idx, j);
            uint2 p = __ldg(&hv[(size_t)s * 32 + lane]);
            float2 a = __half22float2(*(__half2*)&p.x);
            float2 b = __half22float2(*(__half2*)&p.y);
            acc.x += a.x; acc.y += a.y; acc.z += b.x; acc.w += b.y;
        }
        e += cnt;
    }

    float sc = g_dinv[row];
    float4 b = ((const float4*)bias)[lane];
    float4 t;
    t.x = fmaf(acc.x, sc, b.x);
    t.y = fmaf(acc.y, sc, b.y);
    t.z = fmaf(acc.z, sc, b.z);
    t.w = fmaf(acc.w, sc, b.w);

    float s  = t.x + t.y + t.z + t.w;
    float sq = t.x * t.x + t.y * t.y + t.z * t.z + t.w * t.w;
#pragma unroll
    for (int o = 16; o; o >>= 1) {
        s  += __shfl_xor_sync(0xFFFFFFFFu, s,  o);
        sq += __shfl_xor_sync(0xFFFFFFFFu, sq, o);
    }
    float mean = s * (1.0f / 128.0f);
    float var  = sq * (1.0f / 128.0f) - mean * mean;
    float rstd = rsqrtf(var + 1e-5f);

    float4 g = ((const float4*)gma)[lane];
    float4 be = ((const float4*)bet)[lane];
    float4 o;
    float u;
    u = (t.x - mean) * rstd * g.x + be.x; o.x = u > 0.f ? u : expm1f(u);
    u = (t.y - mean) * rstd * g.y + be.y; o.y = u > 0.f ? u : expm1f(u);
    u = (t.z - mean) * rstd * g.z + be.z; o.z = u > 0.f ? u : expm1f(u);
    u = (t.w - mean) * rstd * g.w + be.w; o.w = u > 0.f ? u : expm1f(u);

    ((float4*)(out + (size_t)row * 128))[lane] = o;
}

// ---------------- launch ----------------------------------------------------
extern "C" void kernel_launch(void* const* d_in, const int* in_sizes, int n_in,
                              void* d_out, int out_size)
{
    const float* x   = (const float*)d_in[0];
    const void*  ei  = d_in[1];
    const float* W1  = (const float*)d_in[2];
    const float* b1  = (const float*)d_in[3];
    const float* g1  = (const float*)d_in[4];
    const float* be1 = (const float*)d_in[5];
    const float* W2  = (const float*)d_in[6];
    const float* b2  = (const float*)d_in[7];
    const float* g2  = (const float*)d_in[8];
    const float* be2 = (const float*)d_in[9];

    int N = in_sizes[0] / DD;  if (N > NN)   N = NN;
    int E = in_sizes[1] / 2;   if (E > EMAX) E = EMAX;
    float* out = (float*)d_out;

    __half* hs;
    float* x2;
    void* degi;
    cudaGetSymbolAddress((void**)&hs,  g_hs);
    cudaGetSymbolAddress((void**)&x2,  g_x2);
    cudaGetSymbolAddress(&degi, g_degi);

    const int T = 256;
    int ebl = (E + T - 1) / T;
    int abl = (N + 7) / 8;
    int gbl = (N + 127) / 128;

    // ---- graph preprocessing ----
    cudaMemsetAsync(degi, 0, (size_t)N * sizeof(int));
    k_detect<<<1, 32>>>((const unsigned*)ei);
    k_convert<<<ebl, T>>>(ei, E);
    k_scan<<<1, 1024>>>(N);
    k_fill<<<ebl, T>>>(E);

    // ---- layer 1 ----
    k_gemm<<<gbl, T>>>(x, W1, hs, N);
    k_aggln<<<abl, T>>>(hs, b1, g1, be1, x2, N);

    // ---- layer 2 ----
    k_gemm<<<gbl, T>>>(x2, W2, hs, N);
    k_aggln<<<abl, T>>>(hs, b2, g2, be2, out, N);
}

// round 4
// speedup vs baseline: 1.5710x; 1.0116x over previous
#include <cuda_runtime.h>
#include <cuda_fp16.h>
#include <cstdint>

#define NN   50000
#define DD   128
#define EMAX 1600000

// ---------------- device scratch ----------------
__device__ __align__(16) float g_dinv[NN];
__device__ int g_degi[NN];
__device__ int g_off[NN + 1];
__device__ int g_cur[NN];
__device__ int g_csr[EMAX];
__device__ __align__(16) __half g_hs[(size_t)NN * DD];
__device__ __align__(16) float g_x2[(size_t)NN * DD];
__device__ int g_is64;

// ---------------- per-block int64/int32 detection helper -------------------
// Node ids < 50000 < 2^31, so for int64 data every odd 32-bit word is 0.
__device__ __forceinline__ int detect_is64(const unsigned* ei) {
    unsigned hi = ei[(threadIdx.x & 31) * 2 + 1];
    unsigned any = __ballot_sync(0xFFFFFFFFu, hi != 0u);
    return (any == 0u) ? 1 : 0;
}

// ---------------- degree count (reads edge_index directly) ----------------
__global__ void k_count(const void* __restrict__ ei, int E) {
    __shared__ int s_is64;
    int is64;
    if (threadIdx.x < 32) {
        is64 = detect_is64((const unsigned*)ei);
        if (threadIdx.x == 0) {
            s_is64 = is64;
            if (blockIdx.x == 0) g_is64 = is64;   // publish for k_fill
        }
    }
    __syncthreads();
    int i = blockIdx.x * blockDim.x + threadIdx.x;
    if (i >= E) return;
    int d;
    if (s_is64) d = (int)((const long long*)ei)[(size_t)E + i];
    else        d = ((const int*)ei)[(size_t)E + i];
    atomicAdd(&g_degi[d], 1);
}

// ---------------- single-block scan: offsets, cursors, dinv ---------------
__global__ void __launch_bounds__(1024) k_scan(int N) {
    __shared__ int part[1024];
    const int t = threadIdx.x;
    const int C = (N + 1023) >> 10;
    const int lo = t * C;
    const int hi = min(lo + C, N);

    int s = 0;
    for (int i = lo; i < hi; ++i) s += g_degi[i];
    part[t] = s;
    __syncthreads();
    for (int o = 1; o < 1024; o <<= 1) {
        int v = (t >= o) ? part[t - o] : 0;
        __syncthreads();
        part[t] += v;
        __syncthreads();
    }
    int run = (t > 0) ? part[t - 1] : 0;
    for (int i = lo; i < hi; ++i) {
        int dg = g_degi[i];
        g_off[i] = run;
        g_cur[i] = run;
        g_dinv[i] = rsqrtf((float)(dg + 1));   // +1 self-loop
        run += dg;
    }
    if (t == 0) g_off[N] = part[1023];
}

// ---------------- CSR fill (counting sort of edges by dst) ----------------
__global__ void k_fill(const void* __restrict__ ei, int E) {
    int i = blockIdx.x * blockDim.x + threadIdx.x;
    if (i >= E) return;
    int s, d;
    if (g_is64) {
        const long long* p = (const long long*)ei;
        s = (int)p[i];
        d = (int)p[(size_t)E + i];
    } else {
        const int* p = (const int*)ei;
        s = p[i];
        d = p[(size_t)E + i];
    }
    int pos = atomicAdd(&g_cur[d], 1);
    g_csr[pos] = s;
}

// ---------------- GEMM: HS[N,128] = fp16((X @ W) * dinv[row]) -------------
// 256 threads/block, tile 128x128, thread tile 8 rows x 8 cols
// (cols cg*4..+3 and cg*4+64..+67) via fma.rn.f32x2. Conflict-free LDS.
__global__ void __launch_bounds__(256) k_gemm(
    const float* __restrict__ X, const float* __restrict__ W,
    __half* __restrict__ H, int N)
{
    __shared__ float Ws[32 * 128];   // [k][col]
    __shared__ float Xs[32 * 128];   // [k][row]
    const int tx = threadIdx.x;
    const int row0 = blockIdx.x * 128;
    const int cg = tx & 15;          // cols cg*4..+3 and 64+cg*4..+3
    const int rg = tx >> 4;          // rows rg*8..+7

    unsigned long long acc[8][4];
#pragma unroll
    for (int i = 0; i < 8; ++i)
#pragma unroll
        for (int j = 0; j < 4; ++j) acc[i][j] = 0ull;

    for (int kb = 0; kb < 128; kb += 32) {
        {
            const float4* Wg = (const float4*)(W + (size_t)kb * 128);
            float4* Wsv = (float4*)Ws;
#pragma unroll
            for (int i = 0; i < 4; ++i) Wsv[tx + i * 256] = Wg[tx + i * 256];
        }
        {
            const int r = tx & 127;
            const int half_ = tx >> 7;
            const int grow = row0 + r;
#pragma unroll
            for (int q = 0; q < 4; ++q) {
                int k = half_ * 16 + q * 4;
                float4 v = make_float4(0.f, 0.f, 0.f, 0.f);
                if (grow < N) v = *(const float4*)(X + (size_t)grow * 128 + kb + k);
                Xs[(k + 0) * 128 + r] = v.x;
                Xs[(k + 1) * 128 + r] = v.y;
                Xs[(k + 2) * 128 + r] = v.z;
                Xs[(k + 3) * 128 + r] = v.w;
            }
        }
        __syncthreads();

#pragma unroll
        for (int k = 0; k < 32; ++k) {
            ulonglong2 wA = *(const ulonglong2*)&Ws[k * 128 + cg * 4];
            ulonglong2 wB = *(const ulonglong2*)&Ws[k * 128 + 64 + cg * 4];
            float4 x0 = *(const float4*)&Xs[k * 128 + rg * 8];
            float4 x1 = *(const float4*)&Xs[k * 128 + rg * 8 + 4];
            float xr[8] = {x0.x, x0.y, x0.z, x0.w, x1.x, x1.y, x1.z, x1.w};
#pragma unroll
            for (int i = 0; i < 8; ++i) {
                unsigned long long xx;
                asm("mov.b64 %0, {%1, %1};" : "=l"(xx) : "r"(__float_as_uint(xr[i])));
                asm("fma.rn.f32x2 %0, %1, %2, %0;" : "+l"(acc[i][0]) : "l"(xx), "l"(wA.x));
                asm("fma.rn.f32x2 %0, %1, %2, %0;" : "+l"(acc[i][1]) : "l"(xx), "l"(wA.y));
                asm("fma.rn.f32x2 %0, %1, %2, %0;" : "+l"(acc[i][2]) : "l"(xx), "l"(wB.x));
                asm("fma.rn.f32x2 %0, %1, %2, %0;" : "+l"(acc[i][3]) : "l"(xx), "l"(wB.y));
            }
        }
        __syncthreads();
    }

#pragma unroll
    for (int i = 0; i < 8; ++i) {
        int grow = row0 + rg * 8 + i;
        if (grow < N) {
            float sc = g_dinv[grow];
            uint2 oA, oB;
            {
                float a0 = __uint_as_float((unsigned)acc[i][0]) * sc;
                float a1 = __uint_as_float((unsigned)(acc[i][0] >> 32)) * sc;
                float a2 = __uint_as_float((unsigned)acc[i][1]) * sc;
                float a3 = __uint_as_float((unsigned)(acc[i][1] >> 32)) * sc;
                __half2 h0 = __floats2half2_rn(a0, a1);
                __half2 h1 = __floats2half2_rn(a2, a3);
                oA.x = *(unsigned*)&h0; oA.y = *(unsigned*)&h1;
                float b0 = __uint_as_float((unsigned)acc[i][2]) * sc;
                float b1 = __uint_as_float((unsigned)(acc[i][2] >> 32)) * sc;
                float b2 = __uint_as_float((unsigned)acc[i][3]) * sc;
                float b3 = __uint_as_float((unsigned)(acc[i][3] >> 32)) * sc;
                __half2 h2 = __floats2half2_rn(b0, b1);
                __half2 h3 = __floats2half2_rn(b2, b3);
                oB.x = *(unsigned*)&h2; oB.y = *(unsigned*)&h3;
            }
            *(uint2*)(H + (size_t)grow * 128 + cg * 4) = oA;
            *(uint2*)(H + (size_t)grow * 128 + 64 + cg * 4) = oB;
        }
    }
}

// --------- fused pull-aggregation + bias + LN + ELU ------------------------
// Warp per node. Two edges per step: lanes 0-15 handle even edge, 16-31 odd.
// Each lane loads uint4 (8 halfs = 16B); half-warp covers the 256B row.
__device__ __forceinline__ void add8(uint4 p, float* a) {
    float2 f;
    f = __half22float2(*(__half2*)&p.x); a[0] += f.x; a[1] += f.y;
    f = __half22float2(*(__half2*)&p.y); a[2] += f.x; a[3] += f.y;
    f = __half22float2(*(__half2*)&p.z); a[4] += f.x; a[5] += f.y;
    f = __half22float2(*(__half2*)&p.w); a[6] += f.x; a[7] += f.y;
}
__device__ __forceinline__ void fma8(uint4 p, float m, float* a) {
    float2 f;
    f = __half22float2(*(__half2*)&p.x); a[0] = fmaf(f.x, m, a[0]); a[1] = fmaf(f.y, m, a[1]);
    f = __half22float2(*(__half2*)&p.y); a[2] = fmaf(f.x, m, a[2]); a[3] = fmaf(f.y, m, a[3]);
    f = __half22float2(*(__half2*)&p.z); a[4] = fmaf(f.x, m, a[4]); a[5] = fmaf(f.y, m, a[5]);
    f = __half22float2(*(__half2*)&p.w); a[6] = fmaf(f.x, m, a[6]); a[7] = fmaf(f.y, m, a[7]);
}

__global__ void __launch_bounds__(256) k_aggln(
    const __half* __restrict__ hs, const float* __restrict__ bias,
    const float* __restrict__ gma, const float* __restrict__ bet,
    float* __restrict__ out, int N)
{
    int gt = blockIdx.x * blockDim.x + threadIdx.x;
    int row = gt >> 5;
    int lane = gt & 31;
    if (row >= N) return;
    const int lh = lane >> 4;          // which edge of the pair
    const int lc = lane & 15;          // 16B chunk within row

    const uint4* hv = (const uint4*)hs;   // 16 uint4 per row

    float acc[8];
#pragma unroll
    for (int c = 0; c < 8; ++c) acc[c] = 0.f;
    if (lh == 0) {                      // self-loop term, once
        uint4 p = __ldg(&hv[(size_t)row * 16 + lc]);
        add8(p, acc);
    }

    int e = g_off[row];
    const int end = g_off[row + 1];

    // full batches of 32 edges: statically unrolled -> deep MLP
    while (end - e >= 32) {
        int idx = g_csr[e + lane];
#pragma unroll
        for (int j = 0; j < 32; j += 2) {
            int s = __shfl_sync(0xFFFFFFFFu, idx, j + lh);
            uint4 p = __ldg(&hv[(size_t)s * 16 + lc]);
            add8(p, acc);
        }
        e += 32;
    }
    // remainder (< 32 edges)
    int rem = end - e;
    if (rem > 0) {
        int idx = g_csr[e + min(lane, rem - 1)];
        for (int j = 0; j < rem; j += 2) {
            int jj = j + lh;
            int s = __shfl_sync(0xFFFFFFFFu, idx, min(jj, rem - 1));
            uint4 p = __ldg(&hv[(size_t)s * 16 + lc]);
            float m = (jj < rem) ? 1.f : 0.f;
            fma8(p, m, acc);
        }
    }

    // combine the two edge-halves (lanes L and L^16 hold the same columns)
#pragma unroll
    for (int c = 0; c < 8; ++c)
        acc[c] += __shfl_xor_sync(0xFFFFFFFFu, acc[c], 16);

    // t = acc * dinv + bias
    float sc = g_dinv[row];
    float4 b0 = ((const float4*)bias)[lc * 2];
    float4 b1 = ((const float4*)bias)[lc * 2 + 1];
    float t[8];
    t[0] = fmaf(acc[0], sc, b0.x); t[1] = fmaf(acc[1], sc, b0.y);
    t[2] = fmaf(acc[2], sc, b0.z); t[3] = fmaf(acc[3], sc, b0.w);
    t[4] = fmaf(acc[4], sc, b1.x); t[5] = fmaf(acc[5], sc, b1.y);
    t[6] = fmaf(acc[6], sc, b1.z); t[7] = fmaf(acc[7], sc, b1.w);

    float s = 0.f, sq = 0.f;
#pragma unroll
    for (int c = 0; c < 8; ++c) { s += t[c]; sq += t[c] * t[c]; }
    // reduce within each 16-lane half (halves hold identical data)
#pragma unroll
    for (int o = 8; o; o >>= 1) {
        s  += __shfl_xor_sync(0xFFFFFFFFu, s,  o);
        sq += __shfl_xor_sync(0xFFFFFFFFu, sq, o);
    }
    float mean = s * (1.0f / 128.0f);
    float var  = sq * (1.0f / 128.0f) - mean * mean;
    float rstd = rsqrtf(var + 1e-5f);

    float4 g0 = ((const float4*)gma)[lc * 2];
    float4 g1 = ((const float4*)gma)[lc * 2 + 1];
    float4 e0 = ((const float4*)bet)[lc * 2];
    float4 e1 = ((const float4*)bet)[lc * 2 + 1];
    float gg[8] = {g0.x, g0.y, g0.z, g0.w, g1.x, g1.y, g1.z, g1.w};
    float bb[8] = {e0.x, e0.y, e0.z, e0.w, e1.x, e1.y, e1.z, e1.w};

    if (lh == 0) {
        float o[8];
#pragma unroll
        for (int c = 0; c < 8; ++c) {
            float u = (t[c] - mean) * rstd * gg[c] + bb[c];
            o[c] = u > 0.f ? u : expm1f(u);
        }
        float4* op = (float4*)(out + (size_t)row * 128 + lc * 8);
        op[0] = make_float4(o[0], o[1], o[2], o[3]);
        op[1] = make_float4(o[4], o[5], o[6], o[7]);
    }
}

// ---------------- launch ----------------------------------------------------
extern "C" void kernel_launch(void* const* d_in, const int* in_sizes, int n_in,
                              void* d_out, int out_size)
{
    const float* x   = (const float*)d_in[0];
    const void*  ei  = d_in[1];
    const float* W1  = (const float*)d_in[2];
    const float* b1  = (const float*)d_in[3];
    const float* g1  = (const float*)d_in[4];
    const float* be1 = (const float*)d_in[5];
    const float* W2  = (const float*)d_in[6];
    const float* b2  = (const float*)d_in[7];
    const float* g2  = (const float*)d_in[8];
    const float* be2 = (const float*)d_in[9];

    int N = in_sizes[0] / DD;  if (N > NN)   N = NN;
    int E = in_sizes[1] / 2;   if (E > EMAX) E = EMAX;
    float* out = (float*)d_out;

    __half* hs;
    float* x2;
    void* degi;
    cudaGetSymbolAddress((void**)&hs,  g_hs);
    cudaGetSymbolAddress((void**)&x2,  g_x2);
    cudaGetSymbolAddress(&degi, g_degi);

    const int T = 256;
    int ebl = (E + T - 1) / T;
    int abl = (N + 7) / 8;
    int gbl = (N + 127) / 128;

    // ---- graph preprocessing ----
    cudaMemsetAsync(degi, 0, (size_t)N * sizeof(int));
    k_count<<<ebl, T>>>(ei, E);
    k_scan<<<1, 1024>>>(N);
    k_fill<<<ebl, T>>>(ei, E);

    // ---- layer 1 ----
    k_gemm<<<gbl, T>>>(x, W1, hs, N);
    k_aggln<<<abl, T>>>(hs, b1, g1, be1, x2, N);

    // ---- layer 2 ----
    k_gemm<<<gbl, T>>>(x2, W2, hs, N);
    k_aggln<<<abl, T>>>(hs, b2, g2, be2, out, N);
}